// round 1
// baseline (speedup 1.0000x reference)
#include <cuda_runtime.h>
#include <cuda_bf16.h>

#define CCH 64
#define HH 120
#define WW 120
#define NBOX 4096
#define NPIX (HH*WW)
#define NSAMP 179   // 9 + 49 + 121

__device__ float g_fm_hwc[NPIX * CCH];       // 3.69 MB
__device__ float g_gh[CCH];                  // global-branch head output (shared by all boxes)
__device__ float g_pooled[3 * NBOX * CCH];   // pooled features, row = scale*4096+box
__device__ float g_concat[NBOX * 256];       // cols 0..191 written by head1; 192..255 = gh (filled in final)

// ---------------------------------------------------------------- transpose CHW -> HWC
__global__ void k_transpose(const float* __restrict__ fm) {
    int i = blockIdx.x * blockDim.x + threadIdx.x;
    if (i < NPIX * CCH) {
        int c = i & 63;
        int pix = i >> 6;
        g_fm_hwc[i] = fm[c * NPIX + pix];
    }
}

// ---------------------------------------------------------------- global mean + shared head (once)
__global__ void k_global_head(const float* __restrict__ w1, const float* __restrict__ b1,
                              const float* __restrict__ w2, const float* __restrict__ b2) {
    __shared__ float sred[1024];
    __shared__ float gs[CCH];
    __shared__ float hs[128];
    int t = threadIdx.x;
    float s = 0.f;
    for (int i = t; i < NPIX * CCH; i += 1024) s += g_fm_hwc[i];
    sred[t] = s;
    __syncthreads();
    if (t < 64) {
        float v = 0.f;
        #pragma unroll
        for (int k = 0; k < 16; k++) v += sred[t + 64 * k];
        gs[t] = v * (1.0f / (float)NPIX);
    }
    __syncthreads();
    if (t < 128) {
        float a = b1[t];
        #pragma unroll 8
        for (int c = 0; c < 64; c++) a = fmaf(gs[c], w1[c * 128 + t], a);
        hs[t] = fmaxf(a, 0.f);
    }
    __syncthreads();
    if (t < 64) {
        float a = b2[t];
        #pragma unroll 8
        for (int k = 0; k < 128; k++) a = fmaf(hs[k], w2[k * 64 + t], a);
        g_gh[t] = fmaxf(a, 0.f);
    }
}

// ---------------------------------------------------------------- ROI pooling (one block per box, 64 threads)
__global__ void k_pool(const float* __restrict__ boxes) {
    __shared__ int   soff0[NSAMP], soff1[NSAMP], soff2[NSAMP], soff3[NSAMP];
    __shared__ float sw0[NSAMP], sw1[NSAMP], sw2[NSAMP], sw3[NSAMP];

    int box = blockIdx.x;
    int t = threadIdx.x;  // 64 threads = channel id

    // normalized box (all threads compute; cheap)
    float x1 = boxes[box * 4 + 0] * (2.0f / 960.0f) - 1.0f;
    float y1 = boxes[box * 4 + 1] * (2.0f / 960.0f) - 1.0f;
    float x2 = boxes[box * 4 + 2] * (2.0f / 960.0f) - 1.0f;
    float y2 = boxes[box * 4 + 3] * (2.0f / 960.0f) - 1.0f;
    float cx = 0.5f * (x1 + x2), cy = 0.5f * (y1 + y2);
    float bw2 = 0.5f * fmaxf(x2 - x1, 1e-6f);
    float bh2 = 0.5f * fmaxf(y2 - y1, 1e-6f);

    // phase 1: precompute sample metadata cooperatively
    for (int i = t; i < NSAMP; i += 64) {
        int r, j;
        if (i < 9)       { r = 3;  j = i; }
        else if (i < 58) { r = 7;  j = i - 9; }
        else             { r = 11; j = i - 58; }
        int sy = j / r, sx = j - sy * r;
        float invr = 1.0f / (float)r;
        float liny = (2.0f * sy + 1.0f) * invr - 1.0f;
        float linx = (2.0f * sx + 1.0f) * invr - 1.0f;
        float gy = cy + bh2 * liny;
        float gx = cx + bw2 * linx;
        float iy = ((gy + 1.0f) * (float)HH - 1.0f) * 0.5f;
        float ix = ((gx + 1.0f) * (float)WW - 1.0f) * 0.5f;
        float y0f = floorf(iy), x0f = floorf(ix);
        float wy1 = iy - y0f, wx1 = ix - x0f;
        int y0 = (int)y0f, x0 = (int)x0f;
        int y1i = y0 + 1, x1i = x0 + 1;
        float vx0 = (x0 >= 0 && x0 < WW) ? 1.f : 0.f;
        float vx1 = (x1i >= 0 && x1i < WW) ? 1.f : 0.f;
        float vy0 = (y0 >= 0 && y0 < HH) ? 1.f : 0.f;
        float vy1 = (y1i >= 0 && y1i < HH) ? 1.f : 0.f;
        int x0c = min(max(x0, 0), WW - 1);
        int x1c = min(max(x1i, 0), WW - 1);
        int y0c = min(max(y0, 0), HH - 1);
        int y1c = min(max(y1i, 0), HH - 1);
        soff0[i] = (y0c * WW + x0c) * CCH;
        soff1[i] = (y0c * WW + x1c) * CCH;
        soff2[i] = (y1c * WW + x0c) * CCH;
        soff3[i] = (y1c * WW + x1c) * CCH;
        sw0[i] = (1.f - wx1) * (1.f - wy1) * vx0 * vy0;
        sw1[i] = wx1 * (1.f - wy1) * vx1 * vy0;
        sw2[i] = (1.f - wx1) * wy1 * vx0 * vy1;
        sw3[i] = wx1 * wy1 * vx1 * vy1;
    }
    __syncthreads();

    // phase 2: gather per channel
    const float* fm = g_fm_hwc + t;
    float a0 = 0.f, a1 = 0.f, a2 = 0.f;
    #pragma unroll 3
    for (int i = 0; i < 9; i++) {
        a0 = fmaf(fm[soff0[i]], sw0[i], a0);
        a0 = fmaf(fm[soff1[i]], sw1[i], a0);
        a0 = fmaf(fm[soff2[i]], sw2[i], a0);
        a0 = fmaf(fm[soff3[i]], sw3[i], a0);
    }
    #pragma unroll 7
    for (int i = 9; i < 58; i++) {
        a1 = fmaf(fm[soff0[i]], sw0[i], a1);
        a1 = fmaf(fm[soff1[i]], sw1[i], a1);
        a1 = fmaf(fm[soff2[i]], sw2[i], a1);
        a1 = fmaf(fm[soff3[i]], sw3[i], a1);
    }
    #pragma unroll 11
    for (int i = 58; i < NSAMP; i++) {
        a2 = fmaf(fm[soff0[i]], sw0[i], a2);
        a2 = fmaf(fm[soff1[i]], sw1[i], a2);
        a2 = fmaf(fm[soff2[i]], sw2[i], a2);
        a2 = fmaf(fm[soff3[i]], sw3[i], a2);
    }
    g_pooled[(0 * NBOX + box) * CCH + t] = a0 * (1.0f / 9.0f);
    g_pooled[(1 * NBOX + box) * CCH + t] = a1 * (1.0f / 49.0f);
    g_pooled[(2 * NBOX + box) * CCH + t] = a2 * (1.0f / 121.0f);
}

// ---------------------------------------------------------------- shared head over 3*4096 pooled rows
#define RPB1 8
__global__ void k_head1(const float* __restrict__ w1, const float* __restrict__ b1,
                        const float* __restrict__ w2, const float* __restrict__ b2) {
    extern __shared__ float sm[];
    float* w1s = sm;                 // 64*128 = 8192
    float* w2s = sm + 8192;          // 128*64 = 8192
    float* xs  = sm + 16384;         // RPB1*64 = 512
    float* hs  = sm + 16896;         // RPB1*128 = 1024

    int t = threadIdx.x;  // 128
    for (int i = t; i < 8192; i += 128) { w1s[i] = w1[i]; w2s[i] = w2[i]; }
    float bb1 = b1[t];
    float bb2 = b2[t & 63];
    __syncthreads();

    const int ntiles = (3 * NBOX) / RPB1;  // 1536
    for (int tile = blockIdx.x; tile < ntiles; tile += gridDim.x) {
        int row0 = tile * RPB1;
        for (int i = t; i < RPB1 * 64; i += 128) xs[i] = g_pooled[row0 * 64 + i];
        __syncthreads();

        float acc[RPB1];
        #pragma unroll
        for (int r = 0; r < RPB1; r++) acc[r] = bb1;
        #pragma unroll 4
        for (int c = 0; c < 64; c++) {
            float w = w1s[c * 128 + t];
            #pragma unroll
            for (int r = 0; r < RPB1; r++) acc[r] = fmaf(w, xs[r * 64 + c], acc[r]);
        }
        #pragma unroll
        for (int r = 0; r < RPB1; r++) hs[r * 128 + t] = fmaxf(acc[r], 0.f);
        __syncthreads();

        // layer 2: 128 threads = 64 cols x 2 row-halves
        int col = t & 63;
        int rb = (t >> 6) * (RPB1 / 2);
        float o[RPB1 / 2];
        #pragma unroll
        for (int q = 0; q < RPB1 / 2; q++) o[q] = bb2;
        #pragma unroll 4
        for (int k = 0; k < 128; k++) {
            float w = w2s[k * 64 + col];
            #pragma unroll
            for (int q = 0; q < RPB1 / 2; q++) o[q] = fmaf(w, hs[(rb + q) * 128 + k], o[q]);
        }
        #pragma unroll
        for (int q = 0; q < RPB1 / 2; q++) {
            int gr = row0 + rb + q;
            int scale = gr >> 12;
            int bx = gr & (NBOX - 1);
            g_concat[bx * 256 + scale * 64 + col] = fmaxf(o[q], 0.f);
        }
        __syncthreads();
    }
}

// ---------------------------------------------------------------- final fusion head
#define RPB2 8
__global__ void k_final(const float* __restrict__ p1, const float* __restrict__ pb1,
                        const float* __restrict__ p2, const float* __restrict__ pb2,
                        float* __restrict__ out) {
    extern __shared__ float sm[];
    float* p1s = sm;                  // 256*128 = 32768
    float* p2s = sm + 32768;          // 128*64 = 8192
    float* xs  = sm + 40960;          // RPB2*256 = 2048
    float* hs  = sm + 43008;          // RPB2*128 = 1024
    float* ghs = sm + 44032;          // 64

    int t = threadIdx.x;  // 128
    for (int i = t; i < 32768; i += 128) p1s[i] = p1[i];
    for (int i = t; i < 8192; i += 128) p2s[i] = p2[i];
    if (t < 64) ghs[t] = g_gh[t];
    float bb1 = pb1[t];
    float bb2 = pb2[t & 63];
    __syncthreads();

    const int ntiles = NBOX / RPB2;  // 512
    for (int tile = blockIdx.x; tile < ntiles; tile += gridDim.x) {
        int b0 = tile * RPB2;
        for (int i = t; i < RPB2 * 192; i += 128) {
            int r = i / 192, cc = i - r * 192;
            xs[r * 256 + cc] = g_concat[(b0 + r) * 256 + cc];
        }
        for (int i = t; i < RPB2 * 64; i += 128) {
            int r = i >> 6, j = i & 63;
            xs[r * 256 + 192 + j] = ghs[j];
        }
        __syncthreads();

        float acc[RPB2];
        #pragma unroll
        for (int r = 0; r < RPB2; r++) acc[r] = bb1;
        #pragma unroll 4
        for (int c = 0; c < 256; c++) {
            float w = p1s[c * 128 + t];
            #pragma unroll
            for (int r = 0; r < RPB2; r++) acc[r] = fmaf(w, xs[r * 256 + c], acc[r]);
        }
        #pragma unroll
        for (int r = 0; r < RPB2; r++) hs[r * 128 + t] = fmaxf(acc[r], 0.f);
        __syncthreads();

        int col = t & 63;
        int rb = (t >> 6) * (RPB2 / 2);
        float o[RPB2 / 2];
        #pragma unroll
        for (int q = 0; q < RPB2 / 2; q++) o[q] = bb2;
        #pragma unroll 4
        for (int k = 0; k < 128; k++) {
            float w = p2s[k * 64 + col];
            #pragma unroll
            for (int q = 0; q < RPB2 / 2; q++) o[q] = fmaf(w, hs[(rb + q) * 128 + k], o[q]);
        }
        #pragma unroll
        for (int q = 0; q < RPB2 / 2; q++)
            out[(b0 + rb + q) * 64 + col] = fmaxf(o[q], 0.f);
        __syncthreads();
    }
}

extern "C" void kernel_launch(void* const* d_in, const int* in_sizes, int n_in,
                              void* d_out, int out_size) {
    const float* fm    = (const float*)d_in[0];
    const float* boxes = (const float*)d_in[1];
    const float* w1    = (const float*)d_in[2];
    const float* b1    = (const float*)d_in[3];
    const float* w2    = (const float*)d_in[4];
    const float* b2    = (const float*)d_in[5];
    const float* p1    = (const float*)d_in[6];
    const float* pb1   = (const float*)d_in[7];
    const float* p2    = (const float*)d_in[8];
    const float* pb2   = (const float*)d_in[9];
    float* out = (float*)d_out;

    const int smem1 = 17920 * 4;   // 71680 B
    const int smem2 = 44096 * 4;   // 176384 B
    cudaFuncSetAttribute(k_head1, cudaFuncAttributeMaxDynamicSharedMemorySize, smem1);
    cudaFuncSetAttribute(k_final, cudaFuncAttributeMaxDynamicSharedMemorySize, smem2);

    k_transpose<<<(NPIX * CCH + 255) / 256, 256>>>(fm);
    k_global_head<<<1, 1024>>>(w1, b1, w2, b2);
    k_pool<<<NBOX, 64>>>(boxes);
    k_head1<<<444, 128, smem1>>>(w1, b1, w2, b2);
    k_final<<<148, 128, smem2>>>(p1, pb1, p2, pb2, out);
}

// round 2
// speedup vs baseline: 1.7377x; 1.7377x over previous
#include <cuda_runtime.h>
#include <cuda_fp16.h>

#define CCH 64
#define HH 120
#define WW 120
#define NBOX 4096
#define NPIX (HH*WW)
#define NSAMP 179      // 9 + 49 + 121
#define NTILE 450      // NPIX / 32

__device__ __half g_fm_h[NPIX * CCH];      // fp16 HWC feature map (1.84 MB)
__device__ float  g_part[NTILE * CCH];     // per-tile channel partial sums
__device__ float  g_gh[CCH];               // global-branch head output
__device__ float  g_pooled[3 * NBOX * CCH];
__device__ float  g_concat[NBOX * 256];    // cols 0..191 from head1; 192..255 = gh

// ---------------------------------------------------------------- transpose CHW fp32 -> HWC fp16 (+ channel partial sums)
__global__ void k_transpose(const float* __restrict__ fm) {
    __shared__ float s[64][33];
    int tx = threadIdx.x, ty = threadIdx.y;          // (32, 8)
    int pix0 = blockIdx.x * 32;
    #pragma unroll
    for (int c = ty; c < 64; c += 8)
        s[c][tx] = fm[c * NPIX + pix0 + tx];         // coalesced along pixels
    __syncthreads();
    int t = ty * 32 + tx;                            // 0..255
    // write fp16 HWC: thread -> (pixel p, 8 consecutive channels)
    int p = t >> 3;
    int c0 = (t & 7) * 8;
    __half h[8];
    #pragma unroll
    for (int k = 0; k < 8; k++) h[k] = __float2half_rn(s[c0 + k][p]);
    *reinterpret_cast<uint4*>(&g_fm_h[(pix0 + p) * 64 + c0]) = *reinterpret_cast<uint4*>(h);
    // per-channel partial sum over this 32-pixel tile (deterministic, no atomics)
    int c = t >> 2, q = t & 3;
    float v = 0.f;
    #pragma unroll
    for (int j = 0; j < 8; j++) v += s[c][q * 8 + j];
    v += __shfl_xor_sync(0xffffffffu, v, 1);
    v += __shfl_xor_sync(0xffffffffu, v, 2);
    if (q == 0) g_part[blockIdx.x * 64 + c] = v;
}

// ---------------------------------------------------------------- global mean + shared head (once)
__global__ void k_global_head(const float* __restrict__ w1, const float* __restrict__ b1,
                              const float* __restrict__ w2, const float* __restrict__ b2) {
    __shared__ float sred[256];
    __shared__ float gs[64];
    __shared__ float hs[128];
    int t = threadIdx.x;                             // 256
    int c = t & 63, g = t >> 6;
    float v = 0.f;
    for (int b = g; b < NTILE; b += 4) v += g_part[b * 64 + c];
    sred[t] = v;
    __syncthreads();
    if (t < 64)
        gs[t] = (sred[t] + sred[t + 64] + sred[t + 128] + sred[t + 192]) * (1.0f / (float)NPIX);
    __syncthreads();
    if (t < 128) {
        float a = b1[t];
        #pragma unroll 8
        for (int k = 0; k < 64; k++) a = fmaf(gs[k], w1[k * 128 + t], a);
        hs[t] = fmaxf(a, 0.f);
    }
    __syncthreads();
    if (t < 64) {
        float a = b2[t];
        #pragma unroll 8
        for (int k = 0; k < 128; k++) a = fmaf(hs[k], w2[k * 64 + t], a);
        g_gh[t] = fmaxf(a, 0.f);
    }
}

// ---------------------------------------------------------------- ROI pooling: 4 boxes/block, 64 thr/box = 4 corners x 16 chunks
__global__ void k_pool(const float* __restrict__ boxes) {
    __shared__ int    s_off[4][4][NSAMP];
    __shared__ float  s_w[4][4][NSAMP];
    __shared__ float4 s_red[4][3][16];

    int t = threadIdx.x;                // 256
    int b = t >> 6;                     // box slot 0..3
    int tid = t & 63;
    int box = blockIdx.x * 4 + b;

    float x1 = boxes[box * 4 + 0] * (2.0f / 960.0f) - 1.0f;
    float y1 = boxes[box * 4 + 1] * (2.0f / 960.0f) - 1.0f;
    float x2 = boxes[box * 4 + 2] * (2.0f / 960.0f) - 1.0f;
    float y2 = boxes[box * 4 + 3] * (2.0f / 960.0f) - 1.0f;
    float cx = 0.5f * (x1 + x2), cy = 0.5f * (y1 + y2);
    float bw2 = 0.5f * fmaxf(x2 - x1, 1e-6f);
    float bh2 = 0.5f * fmaxf(y2 - y1, 1e-6f);

    for (int i = tid; i < NSAMP; i += 64) {
        int r, j;
        if (i < 9)       { r = 3;  j = i; }
        else if (i < 58) { r = 7;  j = i - 9; }
        else             { r = 11; j = i - 58; }
        int sy = j / r, sx = j - sy * r;
        float invr = 1.0f / (float)r;
        float liny = (2.0f * sy + 1.0f) * invr - 1.0f;
        float linx = (2.0f * sx + 1.0f) * invr - 1.0f;
        float gy = cy + bh2 * liny;
        float gx = cx + bw2 * linx;
        float iy = ((gy + 1.0f) * (float)HH - 1.0f) * 0.5f;
        float ix = ((gx + 1.0f) * (float)WW - 1.0f) * 0.5f;
        float y0f = floorf(iy), x0f = floorf(ix);
        float wy1 = iy - y0f, wx1 = ix - x0f;
        int y0 = (int)y0f, x0 = (int)x0f;
        int y1i = y0 + 1, x1i = x0 + 1;
        float vx0 = (x0 >= 0 && x0 < WW) ? 1.f : 0.f;
        float vx1 = (x1i >= 0 && x1i < WW) ? 1.f : 0.f;
        float vy0 = (y0 >= 0 && y0 < HH) ? 1.f : 0.f;
        float vy1 = (y1i >= 0 && y1i < HH) ? 1.f : 0.f;
        int x0c = min(max(x0, 0), WW - 1);
        int x1c = min(max(x1i, 0), WW - 1);
        int y0c = min(max(y0, 0), HH - 1);
        int y1c = min(max(y1i, 0), HH - 1);
        s_off[b][0][i] = (y0c * WW + x0c) * 64;
        s_off[b][1][i] = (y0c * WW + x1c) * 64;
        s_off[b][2][i] = (y1c * WW + x0c) * 64;
        s_off[b][3][i] = (y1c * WW + x1c) * 64;
        s_w[b][0][i] = (1.f - wx1) * (1.f - wy1) * vx0 * vy0;
        s_w[b][1][i] = wx1 * (1.f - wy1) * vx1 * vy0;
        s_w[b][2][i] = (1.f - wx1) * wy1 * vx0 * vy1;
        s_w[b][3][i] = wx1 * wy1 * vx1 * vy1;
    }
    __syncthreads();

    int corner = tid >> 4, chunk = tid & 15;
    const int*   off = s_off[b][corner];
    const float* wts = s_w[b][corner];
    float4 a0 = make_float4(0.f, 0.f, 0.f, 0.f);
    float4 a1 = a0, a2 = a0;

#define SAMPLE(ACC, I) { \
        int o = off[I] + chunk * 4; \
        uint2 u = *reinterpret_cast<const uint2*>(&g_fm_h[o]); \
        __half2 h01 = *reinterpret_cast<__half2*>(&u.x); \
        __half2 h23 = *reinterpret_cast<__half2*>(&u.y); \
        float2 f01 = __half22float2(h01); \
        float2 f23 = __half22float2(h23); \
        float w = wts[I]; \
        ACC.x = fmaf(f01.x, w, ACC.x); \
        ACC.y = fmaf(f01.y, w, ACC.y); \
        ACC.z = fmaf(f23.x, w, ACC.z); \
        ACC.w = fmaf(f23.y, w, ACC.w); }

    #pragma unroll 3
    for (int i = 0; i < 9; i++)    SAMPLE(a0, i)
    #pragma unroll 7
    for (int i = 9; i < 58; i++)   SAMPLE(a1, i)
    #pragma unroll 11
    for (int i = 58; i < NSAMP; i++) SAMPLE(a2, i)
#undef SAMPLE

#define RED4(V) { \
        V.x += __shfl_xor_sync(0xffffffffu, V.x, 16); \
        V.y += __shfl_xor_sync(0xffffffffu, V.y, 16); \
        V.z += __shfl_xor_sync(0xffffffffu, V.z, 16); \
        V.w += __shfl_xor_sync(0xffffffffu, V.w, 16); }
    RED4(a0) RED4(a1) RED4(a2)
#undef RED4

    if (tid >= 32 && tid < 48) {     // corners 2+3 partial
        s_red[b][0][chunk] = a0;
        s_red[b][1][chunk] = a1;
        s_red[b][2][chunk] = a2;
    }
    __syncthreads();
    if (tid < 16) {                  // corners 0+1 partial; add & scale
        float4 r0 = s_red[b][0][chunk];
        float4 r1 = s_red[b][1][chunk];
        float4 r2 = s_red[b][2][chunk];
        float4 o0 = make_float4((a0.x + r0.x) * (1.f/9.f),  (a0.y + r0.y) * (1.f/9.f),
                                (a0.z + r0.z) * (1.f/9.f),  (a0.w + r0.w) * (1.f/9.f));
        float4 o1 = make_float4((a1.x + r1.x) * (1.f/49.f), (a1.y + r1.y) * (1.f/49.f),
                                (a1.z + r1.z) * (1.f/49.f), (a1.w + r1.w) * (1.f/49.f));
        float4 o2 = make_float4((a2.x + r2.x) * (1.f/121.f), (a2.y + r2.y) * (1.f/121.f),
                                (a2.z + r2.z) * (1.f/121.f), (a2.w + r2.w) * (1.f/121.f));
        *reinterpret_cast<float4*>(&g_pooled[(0 * NBOX + box) * 64 + chunk * 4]) = o0;
        *reinterpret_cast<float4*>(&g_pooled[(1 * NBOX + box) * 64 + chunk * 4]) = o1;
        *reinterpret_cast<float4*>(&g_pooled[(2 * NBOX + box) * 64 + chunk * 4]) = o2;
    }
}

// ---------------------------------------------------------------- shared head: [12288 x 64] -> relu128 -> relu64
__global__ void k_head1(const float* __restrict__ w1, const float* __restrict__ b1,
                        const float* __restrict__ w2, const float* __restrict__ b2) {
    extern __shared__ float sm[];
    float* w1s = sm;                 // 8192
    float* w2s = sm + 8192;          // 8192
    float* xs  = sm + 16384;         // 16*64
    float* hs  = sm + 17408;         // 16*128

    int t = threadIdx.x;             // 256
    for (int i = t; i < 8192; i += 256) { w1s[i] = w1[i]; w2s[i] = w2[i]; }
    int col2 = t & 63, rowg = t >> 6;           // rowg 0..3 -> 4 rows each
    float bA = b1[col2], bB = b1[col2 + 64];
    float bb2 = b2[col2];
    __syncthreads();

    for (int tile = blockIdx.x; tile < 768; tile += gridDim.x) {
        int row0 = tile * 16;
        for (int i = t; i < 1024; i += 256) xs[i] = g_pooled[row0 * 64 + i];
        __syncthreads();

        float accA[4], accB[4];
        #pragma unroll
        for (int r = 0; r < 4; r++) { accA[r] = bA; accB[r] = bB; }
        #pragma unroll 4
        for (int c = 0; c < 64; c++) {
            float wA = w1s[c * 128 + col2];
            float wB = w1s[c * 128 + col2 + 64];
            #pragma unroll
            for (int r = 0; r < 4; r++) {
                float x = xs[(rowg * 4 + r) * 64 + c];
                accA[r] = fmaf(wA, x, accA[r]);
                accB[r] = fmaf(wB, x, accB[r]);
            }
        }
        #pragma unroll
        for (int r = 0; r < 4; r++) {
            hs[(rowg * 4 + r) * 128 + col2]      = fmaxf(accA[r], 0.f);
            hs[(rowg * 4 + r) * 128 + col2 + 64] = fmaxf(accB[r], 0.f);
        }
        __syncthreads();

        float o[4];
        #pragma unroll
        for (int r = 0; r < 4; r++) o[r] = bb2;
        #pragma unroll 4
        for (int k = 0; k < 128; k++) {
            float w = w2s[k * 64 + col2];
            #pragma unroll
            for (int r = 0; r < 4; r++) o[r] = fmaf(w, hs[(rowg * 4 + r) * 128 + k], o[r]);
        }
        #pragma unroll
        for (int r = 0; r < 4; r++) {
            int gr = row0 + rowg * 4 + r;
            int scale = gr >> 12, bx = gr & 4095;
            g_concat[bx * 256 + scale * 64 + col2] = fmaxf(o[r], 0.f);
        }
        __syncthreads();
    }
}

// ---------------------------------------------------------------- final fusion head: [4096 x 256] -> relu128 -> relu64
__global__ void k_final(const float* __restrict__ p1, const float* __restrict__ pb1,
                        const float* __restrict__ p2, const float* __restrict__ pb2,
                        float* __restrict__ out) {
    extern __shared__ float sm[];
    float* p1s = sm;                 // 32768
    float* p2s = sm + 32768;         // 8192
    float* xs  = sm + 40960;         // 16*256
    float* hs  = sm + 45056;         // 16*128
    float* ghs = sm + 47104;         // 64

    int t = threadIdx.x;             // 512
    for (int i = t; i < 32768; i += 512) p1s[i] = p1[i];
    for (int i = t; i < 8192; i += 512) p2s[i] = p2[i];
    if (t < 64) ghs[t] = g_gh[t];
    int col2 = t & 63, rowg = t >> 6;           // rowg 0..7 -> 2 rows each
    float bA = pb1[col2], bB = pb1[col2 + 64];
    float bb2 = pb2[col2];
    __syncthreads();

    for (int tile = blockIdx.x; tile < 256; tile += gridDim.x) {
        int b0 = tile * 16;
        for (int i = t; i < 4096; i += 512) {
            int r = i >> 8, cc = i & 255;
            xs[i] = (cc < 192) ? g_concat[(b0 + r) * 256 + cc] : ghs[cc - 192];
        }
        __syncthreads();

        int r0 = rowg * 2, r1 = r0 + 1;
        float aA0 = bA, aA1 = bA, aB0 = bB, aB1 = bB;
        #pragma unroll 4
        for (int c = 0; c < 256; c++) {
            float wA = p1s[c * 128 + col2];
            float wB = p1s[c * 128 + col2 + 64];
            float x0 = xs[r0 * 256 + c];
            float x1 = xs[r1 * 256 + c];
            aA0 = fmaf(wA, x0, aA0); aA1 = fmaf(wA, x1, aA1);
            aB0 = fmaf(wB, x0, aB0); aB1 = fmaf(wB, x1, aB1);
        }
        hs[r0 * 128 + col2]      = fmaxf(aA0, 0.f);
        hs[r1 * 128 + col2]      = fmaxf(aA1, 0.f);
        hs[r0 * 128 + col2 + 64] = fmaxf(aB0, 0.f);
        hs[r1 * 128 + col2 + 64] = fmaxf(aB1, 0.f);
        __syncthreads();

        float o0 = bb2, o1 = bb2;
        #pragma unroll 4
        for (int k = 0; k < 128; k++) {
            float w = p2s[k * 64 + col2];
            o0 = fmaf(w, hs[r0 * 128 + k], o0);
            o1 = fmaf(w, hs[r1 * 128 + k], o1);
        }
        out[(b0 + r0) * 64 + col2] = fmaxf(o0, 0.f);
        out[(b0 + r1) * 64 + col2] = fmaxf(o1, 0.f);
        __syncthreads();
    }
}

extern "C" void kernel_launch(void* const* d_in, const int* in_sizes, int n_in,
                              void* d_out, int out_size) {
    const float* fm    = (const float*)d_in[0];
    const float* boxes = (const float*)d_in[1];
    const float* w1    = (const float*)d_in[2];
    const float* b1    = (const float*)d_in[3];
    const float* w2    = (const float*)d_in[4];
    const float* b2    = (const float*)d_in[5];
    const float* p1    = (const float*)d_in[6];
    const float* pb1   = (const float*)d_in[7];
    const float* p2    = (const float*)d_in[8];
    const float* pb2   = (const float*)d_in[9];
    float* out = (float*)d_out;

    const int smem1 = 19456 * 4;     // 77824 B
    const int smem2 = 47168 * 4;     // 188672 B
    cudaFuncSetAttribute(k_head1, cudaFuncAttributeMaxDynamicSharedMemorySize, smem1);
    cudaFuncSetAttribute(k_final, cudaFuncAttributeMaxDynamicSharedMemorySize, smem2);

    k_transpose<<<NTILE, dim3(32, 8)>>>(fm);
    k_global_head<<<1, 256>>>(w1, b1, w2, b2);
    k_pool<<<NBOX / 4, 256>>>(boxes);
    k_head1<<<296, 256, smem1>>>(w1, b1, w2, b2);
    k_final<<<148, 512, smem2>>>(p1, pb1, p2, pb2, out);
}

// round 3
// speedup vs baseline: 2.1658x; 1.2464x over previous
#include <cuda_runtime.h>
#include <cuda_fp16.h>

#define CCH 64
#define HH 120
#define WW 120
#define NBOX 4096
#define NPIX (HH*WW)
#define NSAMP 179      // 9 + 49 + 121
#define NTILE 450      // NPIX / 32

__device__ __half g_fm_h[NPIX * CCH];      // fp16 HWC feature map (1.84 MB)
__device__ float  g_part[NTILE * CCH];     // per-tile channel partial sums
__device__ float  g_gh[CCH];               // global-branch head output
__device__ float  g_pooled[3 * NBOX * CCH];
__device__ float  g_concat[NBOX * 192];    // 3 scales x 64 head outputs per box

// ---------------------------------------------------------------- transpose CHW fp32 -> HWC fp16 (+ channel partial sums)
__global__ void k_transpose(const float* __restrict__ fm) {
    __shared__ float s[64][33];
    int tx = threadIdx.x, ty = threadIdx.y;          // (32, 8)
    int pix0 = blockIdx.x * 32;
    #pragma unroll
    for (int c = ty; c < 64; c += 8)
        s[c][tx] = fm[c * NPIX + pix0 + tx];
    __syncthreads();
    int t = ty * 32 + tx;
    int p = t >> 3;
    int c0 = (t & 7) * 8;
    __half h[8];
    #pragma unroll
    for (int k = 0; k < 8; k++) h[k] = __float2half_rn(s[c0 + k][p]);
    *reinterpret_cast<uint4*>(&g_fm_h[(pix0 + p) * 64 + c0]) = *reinterpret_cast<uint4*>(h);
    int c = t >> 2, q = t & 3;
    float v = 0.f;
    #pragma unroll
    for (int j = 0; j < 8; j++) v += s[c][q * 8 + j];
    v += __shfl_xor_sync(0xffffffffu, v, 1);
    v += __shfl_xor_sync(0xffffffffu, v, 2);
    if (q == 0) g_part[blockIdx.x * 64 + c] = v;
}

// ---------------------------------------------------------------- global mean + shared head (once)
__global__ void k_global_head(const float* __restrict__ w1, const float* __restrict__ b1,
                              const float* __restrict__ w2, const float* __restrict__ b2) {
    __shared__ float sred[256];
    __shared__ float gs[64];
    __shared__ float hs[128];
    int t = threadIdx.x;                             // 256
    int c = t & 63, g = t >> 6;
    float v = 0.f;
    for (int b = g; b < NTILE; b += 4) v += g_part[b * 64 + c];
    sred[t] = v;
    __syncthreads();
    if (t < 64)
        gs[t] = (sred[t] + sred[t + 64] + sred[t + 128] + sred[t + 192]) * (1.0f / (float)NPIX);
    __syncthreads();
    if (t < 128) {
        float a = b1[t];
        #pragma unroll 8
        for (int k = 0; k < 64; k++) a = fmaf(gs[k], w1[k * 128 + t], a);
        hs[t] = fmaxf(a, 0.f);
    }
    __syncthreads();
    if (t < 64) {
        float a = b2[t];
        #pragma unroll 8
        for (int k = 0; k < 128; k++) a = fmaf(hs[k], w2[k * 64 + t], a);
        g_gh[t] = fmaxf(a, 0.f);
    }
}

// ---------------------------------------------------------------- ROI pooling: 4 boxes/block, 64 thr/box = 4 corners x 16 chunks
__global__ void k_pool(const float* __restrict__ boxes) {
    __shared__ int    s_off[4][4][NSAMP];
    __shared__ float  s_w[4][4][NSAMP];
    __shared__ float4 s_red[4][3][16];

    int t = threadIdx.x;                // 256
    int b = t >> 6;
    int tid = t & 63;
    int box = blockIdx.x * 4 + b;

    float x1 = boxes[box * 4 + 0] * (2.0f / 960.0f) - 1.0f;
    float y1 = boxes[box * 4 + 1] * (2.0f / 960.0f) - 1.0f;
    float x2 = boxes[box * 4 + 2] * (2.0f / 960.0f) - 1.0f;
    float y2 = boxes[box * 4 + 3] * (2.0f / 960.0f) - 1.0f;
    float cx = 0.5f * (x1 + x2), cy = 0.5f * (y1 + y2);
    float bw2 = 0.5f * fmaxf(x2 - x1, 1e-6f);
    float bh2 = 0.5f * fmaxf(y2 - y1, 1e-6f);

    for (int i = tid; i < NSAMP; i += 64) {
        int r, j;
        if (i < 9)       { r = 3;  j = i; }
        else if (i < 58) { r = 7;  j = i - 9; }
        else             { r = 11; j = i - 58; }
        int sy = j / r, sx = j - sy * r;
        float invr = 1.0f / (float)r;
        float liny = (2.0f * sy + 1.0f) * invr - 1.0f;
        float linx = (2.0f * sx + 1.0f) * invr - 1.0f;
        float gy = cy + bh2 * liny;
        float gx = cx + bw2 * linx;
        float iy = ((gy + 1.0f) * (float)HH - 1.0f) * 0.5f;
        float ix = ((gx + 1.0f) * (float)WW - 1.0f) * 0.5f;
        float y0f = floorf(iy), x0f = floorf(ix);
        float wy1 = iy - y0f, wx1 = ix - x0f;
        int y0 = (int)y0f, x0 = (int)x0f;
        int y1i = y0 + 1, x1i = x0 + 1;
        float vx0 = (x0 >= 0 && x0 < WW) ? 1.f : 0.f;
        float vx1 = (x1i >= 0 && x1i < WW) ? 1.f : 0.f;
        float vy0 = (y0 >= 0 && y0 < HH) ? 1.f : 0.f;
        float vy1 = (y1i >= 0 && y1i < HH) ? 1.f : 0.f;
        int x0c = min(max(x0, 0), WW - 1);
        int x1c = min(max(x1i, 0), WW - 1);
        int y0c = min(max(y0, 0), HH - 1);
        int y1c = min(max(y1i, 0), HH - 1);
        s_off[b][0][i] = (y0c * WW + x0c) * 64;
        s_off[b][1][i] = (y0c * WW + x1c) * 64;
        s_off[b][2][i] = (y1c * WW + x0c) * 64;
        s_off[b][3][i] = (y1c * WW + x1c) * 64;
        s_w[b][0][i] = (1.f - wx1) * (1.f - wy1) * vx0 * vy0;
        s_w[b][1][i] = wx1 * (1.f - wy1) * vx1 * vy0;
        s_w[b][2][i] = (1.f - wx1) * wy1 * vx0 * vy1;
        s_w[b][3][i] = wx1 * wy1 * vx1 * vy1;
    }
    __syncthreads();

    int corner = tid >> 4, chunk = tid & 15;
    const int*   off = s_off[b][corner];
    const float* wts = s_w[b][corner];
    float4 a0 = make_float4(0.f, 0.f, 0.f, 0.f);
    float4 a1 = a0, a2 = a0;

#define SAMPLE(ACC, I) { \
        int o = off[I] + chunk * 4; \
        uint2 u = *reinterpret_cast<const uint2*>(&g_fm_h[o]); \
        __half2 h01 = *reinterpret_cast<__half2*>(&u.x); \
        __half2 h23 = *reinterpret_cast<__half2*>(&u.y); \
        float2 f01 = __half22float2(h01); \
        float2 f23 = __half22float2(h23); \
        float w = wts[I]; \
        ACC.x = fmaf(f01.x, w, ACC.x); \
        ACC.y = fmaf(f01.y, w, ACC.y); \
        ACC.z = fmaf(f23.x, w, ACC.z); \
        ACC.w = fmaf(f23.y, w, ACC.w); }

    #pragma unroll 3
    for (int i = 0; i < 9; i++)    SAMPLE(a0, i)
    #pragma unroll 7
    for (int i = 9; i < 58; i++)   SAMPLE(a1, i)
    #pragma unroll 11
    for (int i = 58; i < NSAMP; i++) SAMPLE(a2, i)
#undef SAMPLE

#define RED4(V) { \
        V.x += __shfl_xor_sync(0xffffffffu, V.x, 16); \
        V.y += __shfl_xor_sync(0xffffffffu, V.y, 16); \
        V.z += __shfl_xor_sync(0xffffffffu, V.z, 16); \
        V.w += __shfl_xor_sync(0xffffffffu, V.w, 16); }
    RED4(a0) RED4(a1) RED4(a2)
#undef RED4

    if (tid >= 32 && tid < 48) {
        s_red[b][0][chunk] = a0;
        s_red[b][1][chunk] = a1;
        s_red[b][2][chunk] = a2;
    }
    __syncthreads();
    if (tid < 16) {
        float4 r0 = s_red[b][0][chunk];
        float4 r1 = s_red[b][1][chunk];
        float4 r2 = s_red[b][2][chunk];
        float4 o0 = make_float4((a0.x + r0.x) * (1.f/9.f),  (a0.y + r0.y) * (1.f/9.f),
                                (a0.z + r0.z) * (1.f/9.f),  (a0.w + r0.w) * (1.f/9.f));
        float4 o1 = make_float4((a1.x + r1.x) * (1.f/49.f), (a1.y + r1.y) * (1.f/49.f),
                                (a1.z + r1.z) * (1.f/49.f), (a1.w + r1.w) * (1.f/49.f));
        float4 o2 = make_float4((a2.x + r2.x) * (1.f/121.f), (a2.y + r2.y) * (1.f/121.f),
                                (a2.z + r2.z) * (1.f/121.f), (a2.w + r2.w) * (1.f/121.f));
        *reinterpret_cast<float4*>(&g_pooled[(0 * NBOX + box) * 64 + chunk * 4]) = o0;
        *reinterpret_cast<float4*>(&g_pooled[(1 * NBOX + box) * 64 + chunk * 4]) = o1;
        *reinterpret_cast<float4*>(&g_pooled[(2 * NBOX + box) * 64 + chunk * 4]) = o2;
    }
}

// ---------------------------------------------------------------- shared head GEMM: 96 rows/block, grid 128 (single wave)
__global__ void __launch_bounds__(256, 1)
k_head1(const float* __restrict__ w1, const float* __restrict__ b1,
        const float* __restrict__ w2, const float* __restrict__ b2) {
    extern __shared__ float sm[];
    float* w1s = sm;                 // 8192
    float* w2s = sm + 8192;          // 8192
    float* xs  = sm + 16384;         // 96*64  = 6144
    float* h1  = sm + 22528;         // 96*128 = 12288   (total 34816 fl = 139264 B)

    int t = threadIdx.x;             // 256
    int row0 = blockIdx.x * 96;

    for (int i = t; i < 2048; i += 256) {
        reinterpret_cast<float4*>(w1s)[i] = reinterpret_cast<const float4*>(w1)[i];
        reinterpret_cast<float4*>(w2s)[i] = reinterpret_cast<const float4*>(w2)[i];
    }
    for (int i = t; i < 1536; i += 256)
        reinterpret_cast<float4*>(xs)[i] = reinterpret_cast<const float4*>(&g_pooled[row0 * 64])[i];
    __syncthreads();

    // ---- GEMM1: [96 x 64] @ [64 x 128]; thread = 4 cols x 12 rows
    {
        int cg = t & 31, rg = t >> 5;
        int c0 = cg * 4, r0 = rg * 12;
        float4 bias = *reinterpret_cast<const float4*>(&b1[c0]);
        float4 acc[12];
        #pragma unroll
        for (int i = 0; i < 12; i++) acc[i] = bias;
        #pragma unroll 2
        for (int c = 0; c < 64; c++) {
            float4 w = *reinterpret_cast<float4*>(&w1s[c * 128 + c0]);
            #pragma unroll
            for (int i = 0; i < 12; i++) {
                float x = xs[(r0 + i) * 64 + c];
                acc[i].x = fmaf(w.x, x, acc[i].x);
                acc[i].y = fmaf(w.y, x, acc[i].y);
                acc[i].z = fmaf(w.z, x, acc[i].z);
                acc[i].w = fmaf(w.w, x, acc[i].w);
            }
        }
        #pragma unroll
        for (int i = 0; i < 12; i++) {
            float4 v = make_float4(fmaxf(acc[i].x, 0.f), fmaxf(acc[i].y, 0.f),
                                   fmaxf(acc[i].z, 0.f), fmaxf(acc[i].w, 0.f));
            *reinterpret_cast<float4*>(&h1[(r0 + i) * 128 + c0]) = v;
        }
    }
    __syncthreads();

    // ---- GEMM2: [96 x 128] @ [128 x 64]; thread = 4 cols x 6 rows
    {
        int cg = t & 15, rg = t >> 4;
        int c0 = cg * 4, r0 = rg * 6;
        float4 bias = *reinterpret_cast<const float4*>(&b2[c0]);
        float4 acc[6];
        #pragma unroll
        for (int i = 0; i < 6; i++) acc[i] = bias;
        #pragma unroll 2
        for (int k = 0; k < 128; k++) {
            float4 w = *reinterpret_cast<float4*>(&w2s[k * 64 + c0]);
            #pragma unroll
            for (int i = 0; i < 6; i++) {
                float x = h1[(r0 + i) * 128 + k];
                acc[i].x = fmaf(w.x, x, acc[i].x);
                acc[i].y = fmaf(w.y, x, acc[i].y);
                acc[i].z = fmaf(w.z, x, acc[i].z);
                acc[i].w = fmaf(w.w, x, acc[i].w);
            }
        }
        #pragma unroll
        for (int i = 0; i < 6; i++) {
            int gr = row0 + r0 + i;
            int scale = gr >> 12, bx = gr & 4095;
            float4 v = make_float4(fmaxf(acc[i].x, 0.f), fmaxf(acc[i].y, 0.f),
                                   fmaxf(acc[i].z, 0.f), fmaxf(acc[i].w, 0.f));
            *reinterpret_cast<float4*>(&g_concat[bx * 192 + scale * 64 + c0]) = v;
        }
    }
}

// ---------------------------------------------------------------- final fusion GEMM: 32 boxes/block, grid 128 (single wave)
__global__ void __launch_bounds__(256, 1)
k_final(const float* __restrict__ p1, const float* __restrict__ pb1,
        const float* __restrict__ p2, const float* __restrict__ pb2,
        float* __restrict__ out) {
    extern __shared__ float sm[];
    float* p1s = sm;                 // 32768
    float* p2s = sm + 32768;         // 8192
    float* xc  = sm + 40960;         // 32*256 = 8192
    float* h2  = sm + 49152;         // 32*128 = 4096   (total 53248 fl = 212992 B)

    int t = threadIdx.x;             // 256
    int b0 = blockIdx.x * 32;

    for (int i = t; i < 8192; i += 256)
        reinterpret_cast<float4*>(p1s)[i] = reinterpret_cast<const float4*>(p1)[i];
    for (int i = t; i < 2048; i += 256)
        reinterpret_cast<float4*>(p2s)[i] = reinterpret_cast<const float4*>(p2)[i];
    // concat fill: 32 rows x (192 from head1 + 64 gh)
    for (int i = t; i < 32 * 48; i += 256) {     // float4 view of 192 cols
        int r = i / 48, cc = i - r * 48;
        reinterpret_cast<float4*>(&xc[r * 256])[cc] =
            reinterpret_cast<const float4*>(&g_concat[(b0 + r) * 192])[cc];
    }
    for (int i = t; i < 32 * 16; i += 256) {     // float4 view of 64 gh cols
        int r = i >> 4, j = i & 15;
        reinterpret_cast<float4*>(&xc[r * 256 + 192])[j] =
            reinterpret_cast<const float4*>(g_gh)[j];
    }
    __syncthreads();

    // ---- GEMM3: [32 x 256] @ [256 x 128]; thread = 4 cols x 4 rows
    {
        int cg = t & 31, rg = t >> 5;
        int c0 = cg * 4, r0 = rg * 4;
        float4 bias = *reinterpret_cast<const float4*>(&pb1[c0]);
        float4 acc[4];
        #pragma unroll
        for (int i = 0; i < 4; i++) acc[i] = bias;
        #pragma unroll 2
        for (int c = 0; c < 256; c++) {
            float4 w = *reinterpret_cast<float4*>(&p1s[c * 128 + c0]);
            #pragma unroll
            for (int i = 0; i < 4; i++) {
                float x = xc[(r0 + i) * 256 + c];
                acc[i].x = fmaf(w.x, x, acc[i].x);
                acc[i].y = fmaf(w.y, x, acc[i].y);
                acc[i].z = fmaf(w.z, x, acc[i].z);
                acc[i].w = fmaf(w.w, x, acc[i].w);
            }
        }
        #pragma unroll
        for (int i = 0; i < 4; i++) {
            float4 v = make_float4(fmaxf(acc[i].x, 0.f), fmaxf(acc[i].y, 0.f),
                                   fmaxf(acc[i].z, 0.f), fmaxf(acc[i].w, 0.f));
            *reinterpret_cast<float4*>(&h2[(r0 + i) * 128 + c0]) = v;
        }
    }
    __syncthreads();

    // ---- GEMM4: [32 x 128] @ [128 x 64]; thread = 4 cols x 2 rows
    {
        int cg = t & 15, rg = t >> 4;
        int c0 = cg * 4, r0 = rg * 2;
        float4 bias = *reinterpret_cast<const float4*>(&pb2[c0]);
        float4 acc[2];
        acc[0] = bias; acc[1] = bias;
        #pragma unroll 2
        for (int k = 0; k < 128; k++) {
            float4 w = *reinterpret_cast<float4*>(&p2s[k * 64 + c0]);
            #pragma unroll
            for (int i = 0; i < 2; i++) {
                float x = h2[(r0 + i) * 128 + k];
                acc[i].x = fmaf(w.x, x, acc[i].x);
                acc[i].y = fmaf(w.y, x, acc[i].y);
                acc[i].z = fmaf(w.z, x, acc[i].z);
                acc[i].w = fmaf(w.w, x, acc[i].w);
            }
        }
        #pragma unroll
        for (int i = 0; i < 2; i++) {
            float4 v = make_float4(fmaxf(acc[i].x, 0.f), fmaxf(acc[i].y, 0.f),
                                   fmaxf(acc[i].z, 0.f), fmaxf(acc[i].w, 0.f));
            *reinterpret_cast<float4*>(&out[(b0 + r0 + i) * 64 + c0]) = v;
        }
    }
}

extern "C" void kernel_launch(void* const* d_in, const int* in_sizes, int n_in,
                              void* d_out, int out_size) {
    const float* fm    = (const float*)d_in[0];
    const float* boxes = (const float*)d_in[1];
    const float* w1    = (const float*)d_in[2];
    const float* b1    = (const float*)d_in[3];
    const float* w2    = (const float*)d_in[4];
    const float* b2    = (const float*)d_in[5];
    const float* p1    = (const float*)d_in[6];
    const float* pb1   = (const float*)d_in[7];
    const float* p2    = (const float*)d_in[8];
    const float* pb2   = (const float*)d_in[9];
    float* out = (float*)d_out;

    const int smem1 = 34816 * 4;     // 139264 B
    const int smem2 = 53248 * 4;     // 212992 B
    cudaFuncSetAttribute(k_head1, cudaFuncAttributeMaxDynamicSharedMemorySize, smem1);
    cudaFuncSetAttribute(k_final, cudaFuncAttributeMaxDynamicSharedMemorySize, smem2);

    k_transpose<<<NTILE, dim3(32, 8)>>>(fm);
    k_global_head<<<1, 256>>>(w1, b1, w2, b2);
    k_pool<<<NBOX / 4, 256>>>(boxes);
    k_head1<<<128, 256, smem1>>>(w1, b1, w2, b2);
    k_final<<<128, 256, smem2>>>(p1, pb1, p2, pb2, out);
}

// round 4
// speedup vs baseline: 2.2190x; 1.0245x over previous
#include <cuda_runtime.h>
#include <cuda_fp16.h>

#define CCH 64
#define HH 120
#define WW 120
#define NBOX 4096
#define NPIX (HH*WW)
#define NSAMP 179      // 9 + 49 + 121
#define NTILE 450      // NPIX / 32

typedef unsigned long long ull;

__device__ __half g_fm_h[NPIX * CCH];      // fp16 HWC feature map (1.84 MB)
__device__ float  g_part[NTILE * CCH];     // per-tile channel partial sums
__device__ float  g_gh[CCH];               // global-branch head output
__device__ float  g_pooled[3 * NBOX * CCH];
__device__ float  g_concat[NBOX * 192];    // 3 scales x 64 head outputs per box

// ---- packed fp32x2 helpers (FFMA2) ----
__device__ __forceinline__ ull pk2(float lo, float hi) {
    ull r;
    asm("mov.b64 %0, {%1, %2};" : "=l"(r) : "r"(__float_as_uint(lo)), "r"(__float_as_uint(hi)));
    return r;
}
__device__ __forceinline__ float2 upk(ull v) {
    unsigned lo, hi;
    asm("mov.b64 {%0, %1}, %2;" : "=r"(lo), "=r"(hi) : "l"(v));
    return make_float2(__uint_as_float(lo), __uint_as_float(hi));
}
#define FFMA2(D, A, B) asm("fma.rn.f32x2 %0, %1, %2, %0;" : "+l"(D) : "l"(A), "l"(B))

// ---------------------------------------------------------------- transpose CHW fp32 -> HWC fp16 (+ channel partial sums)
__global__ void k_transpose(const float* __restrict__ fm) {
    __shared__ float s[64][33];
    int tx = threadIdx.x, ty = threadIdx.y;          // (32, 8)
    int pix0 = blockIdx.x * 32;
    #pragma unroll
    for (int c = ty; c < 64; c += 8)
        s[c][tx] = fm[c * NPIX + pix0 + tx];
    __syncthreads();
    int t = ty * 32 + tx;
    int p = t >> 3;
    int c0 = (t & 7) * 8;
    __half h[8];
    #pragma unroll
    for (int k = 0; k < 8; k++) h[k] = __float2half_rn(s[c0 + k][p]);
    *reinterpret_cast<uint4*>(&g_fm_h[(pix0 + p) * 64 + c0]) = *reinterpret_cast<uint4*>(h);
    int c = t >> 2, q = t & 3;
    float v = 0.f;
    #pragma unroll
    for (int j = 0; j < 8; j++) v += s[c][q * 8 + j];
    v += __shfl_xor_sync(0xffffffffu, v, 1);
    v += __shfl_xor_sync(0xffffffffu, v, 2);
    if (q == 0) g_part[blockIdx.x * 64 + c] = v;
}

// ---------------------------------------------------------------- ROI pooling: 4 boxes/block, 64 thr/box = 4 corners x 16 chunks
__global__ void k_pool(const float* __restrict__ boxes) {
    __shared__ int    s_off[4][4][NSAMP];
    __shared__ float  s_w[4][4][NSAMP];
    __shared__ float4 s_red[4][3][16];

    int t = threadIdx.x;                // 256
    int b = t >> 6;
    int tid = t & 63;
    int box = blockIdx.x * 4 + b;

    float x1 = boxes[box * 4 + 0] * (2.0f / 960.0f) - 1.0f;
    float y1 = boxes[box * 4 + 1] * (2.0f / 960.0f) - 1.0f;
    float x2 = boxes[box * 4 + 2] * (2.0f / 960.0f) - 1.0f;
    float y2 = boxes[box * 4 + 3] * (2.0f / 960.0f) - 1.0f;
    float cx = 0.5f * (x1 + x2), cy = 0.5f * (y1 + y2);
    float bw2 = 0.5f * fmaxf(x2 - x1, 1e-6f);
    float bh2 = 0.5f * fmaxf(y2 - y1, 1e-6f);

    for (int i = tid; i < NSAMP; i += 64) {
        int r, j;
        if (i < 9)       { r = 3;  j = i; }
        else if (i < 58) { r = 7;  j = i - 9; }
        else             { r = 11; j = i - 58; }
        int sy = j / r, sx = j - sy * r;
        float invr = 1.0f / (float)r;
        float liny = (2.0f * sy + 1.0f) * invr - 1.0f;
        float linx = (2.0f * sx + 1.0f) * invr - 1.0f;
        float gy = cy + bh2 * liny;
        float gx = cx + bw2 * linx;
        float iy = ((gy + 1.0f) * (float)HH - 1.0f) * 0.5f;
        float ix = ((gx + 1.0f) * (float)WW - 1.0f) * 0.5f;
        float y0f = floorf(iy), x0f = floorf(ix);
        float wy1 = iy - y0f, wx1 = ix - x0f;
        int y0 = (int)y0f, x0 = (int)x0f;
        int y1i = y0 + 1, x1i = x0 + 1;
        float vx0 = (x0 >= 0 && x0 < WW) ? 1.f : 0.f;
        float vx1 = (x1i >= 0 && x1i < WW) ? 1.f : 0.f;
        float vy0 = (y0 >= 0 && y0 < HH) ? 1.f : 0.f;
        float vy1 = (y1i >= 0 && y1i < HH) ? 1.f : 0.f;
        int x0c = min(max(x0, 0), WW - 1);
        int x1c = min(max(x1i, 0), WW - 1);
        int y0c = min(max(y0, 0), HH - 1);
        int y1c = min(max(y1i, 0), HH - 1);
        s_off[b][0][i] = (y0c * WW + x0c) * 64;
        s_off[b][1][i] = (y0c * WW + x1c) * 64;
        s_off[b][2][i] = (y1c * WW + x0c) * 64;
        s_off[b][3][i] = (y1c * WW + x1c) * 64;
        s_w[b][0][i] = (1.f - wx1) * (1.f - wy1) * vx0 * vy0;
        s_w[b][1][i] = wx1 * (1.f - wy1) * vx1 * vy0;
        s_w[b][2][i] = (1.f - wx1) * wy1 * vx0 * vy1;
        s_w[b][3][i] = wx1 * wy1 * vx1 * vy1;
    }
    __syncthreads();

    int corner = tid >> 4, chunk = tid & 15;
    const int*   off = s_off[b][corner];
    const float* wts = s_w[b][corner];
    float4 a0 = make_float4(0.f, 0.f, 0.f, 0.f);
    float4 a1 = a0, a2 = a0;

#define SAMPLE(ACC, I) { \
        int o = off[I] + chunk * 4; \
        uint2 u = *reinterpret_cast<const uint2*>(&g_fm_h[o]); \
        __half2 h01 = *reinterpret_cast<__half2*>(&u.x); \
        __half2 h23 = *reinterpret_cast<__half2*>(&u.y); \
        float2 f01 = __half22float2(h01); \
        float2 f23 = __half22float2(h23); \
        float w = wts[I]; \
        ACC.x = fmaf(f01.x, w, ACC.x); \
        ACC.y = fmaf(f01.y, w, ACC.y); \
        ACC.z = fmaf(f23.x, w, ACC.z); \
        ACC.w = fmaf(f23.y, w, ACC.w); }

    #pragma unroll 3
    for (int i = 0; i < 9; i++)    SAMPLE(a0, i)
    #pragma unroll 7
    for (int i = 9; i < 58; i++)   SAMPLE(a1, i)
    #pragma unroll 11
    for (int i = 58; i < NSAMP; i++) SAMPLE(a2, i)
#undef SAMPLE

#define RED4(V) { \
        V.x += __shfl_xor_sync(0xffffffffu, V.x, 16); \
        V.y += __shfl_xor_sync(0xffffffffu, V.y, 16); \
        V.z += __shfl_xor_sync(0xffffffffu, V.z, 16); \
        V.w += __shfl_xor_sync(0xffffffffu, V.w, 16); }
    RED4(a0) RED4(a1) RED4(a2)
#undef RED4

    if (tid >= 32 && tid < 48) {
        s_red[b][0][chunk] = a0;
        s_red[b][1][chunk] = a1;
        s_red[b][2][chunk] = a2;
    }
    __syncthreads();
    if (tid < 16) {
        float4 r0 = s_red[b][0][chunk];
        float4 r1 = s_red[b][1][chunk];
        float4 r2 = s_red[b][2][chunk];
        float4 o0 = make_float4((a0.x + r0.x) * (1.f/9.f),  (a0.y + r0.y) * (1.f/9.f),
                                (a0.z + r0.z) * (1.f/9.f),  (a0.w + r0.w) * (1.f/9.f));
        float4 o1 = make_float4((a1.x + r1.x) * (1.f/49.f), (a1.y + r1.y) * (1.f/49.f),
                                (a1.z + r1.z) * (1.f/49.f), (a1.w + r1.w) * (1.f/49.f));
        float4 o2 = make_float4((a2.x + r2.x) * (1.f/121.f), (a2.y + r2.y) * (1.f/121.f),
                                (a2.z + r2.z) * (1.f/121.f), (a2.w + r2.w) * (1.f/121.f));
        *reinterpret_cast<float4*>(&g_pooled[(0 * NBOX + box) * 64 + chunk * 4]) = o0;
        *reinterpret_cast<float4*>(&g_pooled[(1 * NBOX + box) * 64 + chunk * 4]) = o1;
        *reinterpret_cast<float4*>(&g_pooled[(2 * NBOX + box) * 64 + chunk * 4]) = o2;
    }
}

// ---------------------------------------------------------------- shared head GEMM (FFMA2): 96 rows/block, grid 128, 512 thr
// smem floats: w1s[8192] w2s[8192] xsT[64*98=6272] h1T[128*98=12544]  = 35200 fl = 140800 B
__global__ void __launch_bounds__(512, 1)
k_head1(const float* __restrict__ w1, const float* __restrict__ b1,
        const float* __restrict__ w2, const float* __restrict__ b2) {
    extern __shared__ float sm[];
    float* w1s = sm;
    float* w2s = sm + 8192;
    float* xsT = sm + 16384;
    float* h1T = sm + 22656;

    int t = threadIdx.x;
    int row0 = blockIdx.x * 96;

    for (int i = t; i < 2048; i += 512) {
        reinterpret_cast<float4*>(w1s)[i] = reinterpret_cast<const float4*>(w1)[i];
        reinterpret_cast<float4*>(w2s)[i] = reinterpret_cast<const float4*>(w2)[i];
    }
    for (int i = t; i < 6144; i += 512) {
        int r = i >> 6, c = i & 63;
        xsT[c * 98 + r] = g_pooled[row0 * 64 + i];
    }
    __syncthreads();

    int lane = t & 31, w = t >> 5;

    // ---- GEMM1: [96 x 64] @ [64 x 128] -> h1T. warps 4x4, lanes 8x4, C=4 cols, 3 row-pairs
    {
        int wc = w & 3, wr = w >> 2;
        int cl = lane & 7, rl = lane >> 3;
        int c0 = wc * 32 + cl * 4;
        int r0 = wr * 24 + rl * 6;
        float4 bv = *reinterpret_cast<const float4*>(&b1[c0]);
        ull acc[4][3];
        #pragma unroll
        for (int j = 0; j < 3; j++) {
            acc[0][j] = pk2(bv.x, bv.x); acc[1][j] = pk2(bv.y, bv.y);
            acc[2][j] = pk2(bv.z, bv.z); acc[3][j] = pk2(bv.w, bv.w);
        }
        #pragma unroll 4
        for (int c = 0; c < 64; c++) {
            float4 wv = *reinterpret_cast<float4*>(&w1s[c * 128 + c0]);
            ull wd0 = pk2(wv.x, wv.x), wd1 = pk2(wv.y, wv.y);
            ull wd2 = pk2(wv.z, wv.z), wd3 = pk2(wv.w, wv.w);
            ull xp0 = *reinterpret_cast<ull*>(&xsT[c * 98 + r0]);
            ull xp1 = *reinterpret_cast<ull*>(&xsT[c * 98 + r0 + 2]);
            ull xp2 = *reinterpret_cast<ull*>(&xsT[c * 98 + r0 + 4]);
            FFMA2(acc[0][0], wd0, xp0); FFMA2(acc[0][1], wd0, xp1); FFMA2(acc[0][2], wd0, xp2);
            FFMA2(acc[1][0], wd1, xp0); FFMA2(acc[1][1], wd1, xp1); FFMA2(acc[1][2], wd1, xp2);
            FFMA2(acc[2][0], wd2, xp0); FFMA2(acc[2][1], wd2, xp1); FFMA2(acc[2][2], wd2, xp2);
            FFMA2(acc[3][0], wd3, xp0); FFMA2(acc[3][1], wd3, xp1); FFMA2(acc[3][2], wd3, xp2);
        }
        #pragma unroll
        for (int ci = 0; ci < 4; ci++)
            #pragma unroll
            for (int j = 0; j < 3; j++) {
                float2 v = upk(acc[ci][j]);
                v.x = fmaxf(v.x, 0.f); v.y = fmaxf(v.y, 0.f);
                *reinterpret_cast<float2*>(&h1T[(c0 + ci) * 98 + r0 + 2 * j]) = v;
            }
    }
    __syncthreads();

    // ---- GEMM2: [96 x 128] @ [128 x 64] -> g_concat. warps 2x8, lanes 16x2, C=2 cols, 3 row-pairs
    {
        int wc = w & 1, wr = w >> 1;
        int cl = lane & 15, rl = lane >> 4;
        int c0 = wc * 32 + cl * 2;
        int r0 = wr * 12 + rl * 6;
        float b20 = b2[c0], b21 = b2[c0 + 1];
        ull acc[2][3];
        #pragma unroll
        for (int j = 0; j < 3; j++) { acc[0][j] = pk2(b20, b20); acc[1][j] = pk2(b21, b21); }
        #pragma unroll 4
        for (int k = 0; k < 128; k++) {
            float2 wv = *reinterpret_cast<float2*>(&w2s[k * 64 + c0]);
            ull wd0 = pk2(wv.x, wv.x), wd1 = pk2(wv.y, wv.y);
            ull xp0 = *reinterpret_cast<ull*>(&h1T[k * 98 + r0]);
            ull xp1 = *reinterpret_cast<ull*>(&h1T[k * 98 + r0 + 2]);
            ull xp2 = *reinterpret_cast<ull*>(&h1T[k * 98 + r0 + 4]);
            FFMA2(acc[0][0], wd0, xp0); FFMA2(acc[0][1], wd0, xp1); FFMA2(acc[0][2], wd0, xp2);
            FFMA2(acc[1][0], wd1, xp0); FFMA2(acc[1][1], wd1, xp1); FFMA2(acc[1][2], wd1, xp2);
        }
        #pragma unroll
        for (int j = 0; j < 3; j++) {
            float2 A = upk(acc[0][j]);
            float2 B = upk(acc[1][j]);
            int gr0 = row0 + r0 + 2 * j;
            int s0 = gr0 >> 12, bx0 = gr0 & 4095;
            *reinterpret_cast<float2*>(&g_concat[bx0 * 192 + s0 * 64 + c0]) =
                make_float2(fmaxf(A.x, 0.f), fmaxf(B.x, 0.f));
            int gr1 = gr0 + 1;
            int s1 = gr1 >> 12, bx1 = gr1 & 4095;
            *reinterpret_cast<float2*>(&g_concat[bx1 * 192 + s1 * 64 + c0]) =
                make_float2(fmaxf(A.y, 0.f), fmaxf(B.y, 0.f));
        }
    }

    // ---- block 0 tail: global-mean shared head (uses w1s/w2s still in smem)
    if (blockIdx.x == 0) {
        __syncthreads();
        float* sred = xsT;          // reuse: [512] + gs[64] + hs[128]
        float* gs   = xsT + 512;
        float* hs   = xsT + 576;
        int c = t & 63, g = t >> 6;
        float v = 0.f;
        for (int bb = g; bb < NTILE; bb += 8) v += g_part[bb * 64 + c];
        sred[t] = v;
        __syncthreads();
        if (t < 64) {
            float s = 0.f;
            #pragma unroll
            for (int q = 0; q < 8; q++) s += sred[t + 64 * q];
            gs[t] = s * (1.0f / (float)NPIX);
        }
        __syncthreads();
        if (t < 128) {
            float a = b1[t];
            #pragma unroll 8
            for (int k = 0; k < 64; k++) a = fmaf(gs[k], w1s[k * 128 + t], a);
            hs[t] = fmaxf(a, 0.f);
        }
        __syncthreads();
        if (t < 64) {
            float a = b2[t];
            #pragma unroll 8
            for (int k = 0; k < 128; k++) a = fmaf(hs[k], w2s[k * 64 + t], a);
            g_gh[t] = fmaxf(a, 0.f);
        }
    }
}

// ---------------------------------------------------------------- final fusion GEMM (FFMA2): 32 boxes/block, grid 128, 512 thr
// smem floats: p1s[32768] p2s[8192] xcT[256*34=8704] h2T[128*34=4352] = 54016 fl = 216064 B
__global__ void __launch_bounds__(512, 1)
k_final(const float* __restrict__ p1, const float* __restrict__ pb1,
        const float* __restrict__ p2, const float* __restrict__ pb2,
        float* __restrict__ out) {
    extern __shared__ float sm[];
    float* p1s = sm;
    float* p2s = sm + 32768;
    float* xcT = sm + 40960;
    float* h2T = sm + 49664;

    int t = threadIdx.x;
    int b0 = blockIdx.x * 32;

    for (int i = t; i < 8192; i += 512)
        reinterpret_cast<float4*>(p1s)[i] = reinterpret_cast<const float4*>(p1)[i];
    for (int i = t; i < 2048; i += 512)
        reinterpret_cast<float4*>(p2s)[i] = reinterpret_cast<const float4*>(p2)[i];
    for (int i = t; i < 8192; i += 512) {
        int r = i >> 8, k = i & 255;
        float v = (k < 192) ? g_concat[(b0 + r) * 192 + k] : g_gh[k - 192];
        xcT[k * 34 + r] = v;
    }
    __syncthreads();

    int lane = t & 31, w = t >> 5;

    // ---- GEMM3: [32 x 256] @ [256 x 128] -> h2T. warps 4x4, lanes 8x4, col-paired C=4, R=2
    {
        int wc = w & 3, wr = w >> 2;
        int cl = lane & 7, rl = lane >> 3;
        int c0 = wc * 32 + cl * 4;
        int r0 = wr * 8 + rl * 2;
        float4 bv = *reinterpret_cast<const float4*>(&pb1[c0]);
        ull acc[2][2];
        acc[0][0] = pk2(bv.x, bv.y); acc[0][1] = acc[0][0];
        acc[1][0] = pk2(bv.z, bv.w); acc[1][1] = acc[1][0];
        #pragma unroll 4
        for (int c = 0; c < 256; c++) {
            ulonglong2 wp = *reinterpret_cast<ulonglong2*>(&p1s[c * 128 + c0]);
            float x0 = xcT[c * 34 + r0];
            float x1 = xcT[c * 34 + r0 + 1];
            ull xd0 = pk2(x0, x0), xd1 = pk2(x1, x1);
            FFMA2(acc[0][0], wp.x, xd0); FFMA2(acc[0][1], wp.x, xd1);
            FFMA2(acc[1][0], wp.y, xd0); FFMA2(acc[1][1], wp.y, xd1);
        }
        #pragma unroll
        for (int cp = 0; cp < 2; cp++)
            #pragma unroll
            for (int r = 0; r < 2; r++) {
                float2 v = upk(acc[cp][r]);
                h2T[(c0 + 2 * cp)     * 34 + r0 + r] = fmaxf(v.x, 0.f);
                h2T[(c0 + 2 * cp + 1) * 34 + r0 + r] = fmaxf(v.y, 0.f);
            }
    }
    __syncthreads();

    // ---- GEMM4: [32 x 128] @ [128 x 64] -> out. warps 2x8, lanes 16x2, C=2, 1 row-pair
    {
        int wc = w & 1, wr = w >> 1;
        int cl = lane & 15, rl = lane >> 4;
        int c0 = wc * 32 + cl * 2;
        int r0 = wr * 4 + rl * 2;
        float b0v = pb2[c0], b1v = pb2[c0 + 1];
        ull acc0 = pk2(b0v, b0v), acc1 = pk2(b1v, b1v);
        #pragma unroll 4
        for (int k = 0; k < 128; k++) {
            float2 wv = *reinterpret_cast<float2*>(&p2s[k * 64 + c0]);
            ull xp = *reinterpret_cast<ull*>(&h2T[k * 34 + r0]);
            ull wd0 = pk2(wv.x, wv.x), wd1 = pk2(wv.y, wv.y);
            FFMA2(acc0, wd0, xp);
            FFMA2(acc1, wd1, xp);
        }
        float2 A = upk(acc0);   // rows r0, r0+1 of col c0
        float2 B = upk(acc1);   // rows r0, r0+1 of col c0+1
        *reinterpret_cast<float2*>(&out[(b0 + r0) * 64 + c0]) =
            make_float2(fmaxf(A.x, 0.f), fmaxf(B.x, 0.f));
        *reinterpret_cast<float2*>(&out[(b0 + r0 + 1) * 64 + c0]) =
            make_float2(fmaxf(A.y, 0.f), fmaxf(B.y, 0.f));
    }
}

extern "C" void kernel_launch(void* const* d_in, const int* in_sizes, int n_in,
                              void* d_out, int out_size) {
    const float* fm    = (const float*)d_in[0];
    const float* boxes = (const float*)d_in[1];
    const float* w1    = (const float*)d_in[2];
    const float* b1    = (const float*)d_in[3];
    const float* w2    = (const float*)d_in[4];
    const float* b2    = (const float*)d_in[5];
    const float* p1    = (const float*)d_in[6];
    const float* pb1   = (const float*)d_in[7];
    const float* p2    = (const float*)d_in[8];
    const float* pb2   = (const float*)d_in[9];
    float* out = (float*)d_out;

    const int smem1 = 35200 * 4;     // 140800 B
    const int smem2 = 54016 * 4;     // 216064 B
    cudaFuncSetAttribute(k_head1, cudaFuncAttributeMaxDynamicSharedMemorySize, smem1);
    cudaFuncSetAttribute(k_final, cudaFuncAttributeMaxDynamicSharedMemorySize, smem2);

    k_transpose<<<NTILE, dim3(32, 8)>>>(fm);
    k_pool<<<NBOX / 4, 256>>>(boxes);
    k_head1<<<128, 512, smem1>>>(w1, b1, w2, b2);
    k_final<<<128, 512, smem2>>>(p1, pb1, p2, pb2, out);
}

// round 5
// speedup vs baseline: 2.6875x; 1.2112x over previous
#include <cuda_runtime.h>
#include <cuda_fp16.h>
#include <mma.h>
using namespace nvcuda;

#define CCH 64
#define HH 120
#define WW 120
#define NBOX 4096
#define NPIX (HH*WW)
#define NSAMP 179      // 9 + 49 + 121
#define NTILE 450      // NPIX / 32

__device__ __half g_fm_h[NPIX * CCH];       // fp16 HWC feature map
__device__ float  g_part[NTILE * CCH];      // per-tile channel partial sums
__device__ __half g_gh_h[CCH];              // global-branch head output (fp16)
__device__ __half g_pooled_h[3 * NBOX * CCH];
__device__ __half g_concat_h[NBOX * 192];   // 3 scales x 64 per box

// padded fp16 weights (conflict-free ldm)
__device__ __half g_w1h[64 * 136];
__device__ __half g_w2h[128 * 72];
__device__ __half g_p1h[256 * 136];
__device__ __half g_p2h[128 * 72];

// ---------------------------------------------------------------- weight convert fp32 -> padded fp16
__global__ void k_wconv(const float* __restrict__ w1, const float* __restrict__ w2,
                        const float* __restrict__ p1, const float* __restrict__ p2) {
    int tid = blockIdx.x * blockDim.x + threadIdx.x;
    int nt = gridDim.x * blockDim.x;
    for (int i = tid; i < 8192; i += nt)  g_w1h[(i >> 7) * 136 + (i & 127)] = __float2half_rn(w1[i]);
    for (int i = tid; i < 8192; i += nt)  g_w2h[(i >> 6) * 72  + (i & 63)]  = __float2half_rn(w2[i]);
    for (int i = tid; i < 32768; i += nt) g_p1h[(i >> 7) * 136 + (i & 127)] = __float2half_rn(p1[i]);
    for (int i = tid; i < 8192; i += nt)  g_p2h[(i >> 6) * 72  + (i & 63)]  = __float2half_rn(p2[i]);
}

// ---------------------------------------------------------------- transpose CHW fp32 -> HWC fp16 (+ channel partial sums)
__global__ void k_transpose(const float* __restrict__ fm) {
    __shared__ float s[64][33];
    int tx = threadIdx.x, ty = threadIdx.y;          // (32, 8)
    int pix0 = blockIdx.x * 32;
    #pragma unroll
    for (int c = ty; c < 64; c += 8)
        s[c][tx] = fm[c * NPIX + pix0 + tx];
    __syncthreads();
    int t = ty * 32 + tx;
    int p = t >> 3;
    int c0 = (t & 7) * 8;
    __half h[8];
    #pragma unroll
    for (int k = 0; k < 8; k++) h[k] = __float2half_rn(s[c0 + k][p]);
    *reinterpret_cast<uint4*>(&g_fm_h[(pix0 + p) * 64 + c0]) = *reinterpret_cast<uint4*>(h);
    int c = t >> 2, q = t & 3;
    float v = 0.f;
    #pragma unroll
    for (int j = 0; j < 8; j++) v += s[c][q * 8 + j];
    v += __shfl_xor_sync(0xffffffffu, v, 1);
    v += __shfl_xor_sync(0xffffffffu, v, 2);
    if (q == 0) g_part[blockIdx.x * 64 + c] = v;
}

// ---------------------------------------------------------------- ROI pooling: 4 boxes/block, 64 thr/box = 4 corners x 16 chunks
__global__ void k_pool(const float* __restrict__ boxes) {
    __shared__ int    s_off[4][4][NSAMP];
    __shared__ float  s_w[4][4][NSAMP];
    __shared__ float4 s_red[4][3][16];

    int t = threadIdx.x;                // 256
    int b = t >> 6;
    int tid = t & 63;
    int box = blockIdx.x * 4 + b;

    float x1 = boxes[box * 4 + 0] * (2.0f / 960.0f) - 1.0f;
    float y1 = boxes[box * 4 + 1] * (2.0f / 960.0f) - 1.0f;
    float x2 = boxes[box * 4 + 2] * (2.0f / 960.0f) - 1.0f;
    float y2 = boxes[box * 4 + 3] * (2.0f / 960.0f) - 1.0f;
    float cx = 0.5f * (x1 + x2), cy = 0.5f * (y1 + y2);
    float bw2 = 0.5f * fmaxf(x2 - x1, 1e-6f);
    float bh2 = 0.5f * fmaxf(y2 - y1, 1e-6f);

    for (int i = tid; i < NSAMP; i += 64) {
        int r, j;
        if (i < 9)       { r = 3;  j = i; }
        else if (i < 58) { r = 7;  j = i - 9; }
        else             { r = 11; j = i - 58; }
        int sy = j / r, sx = j - sy * r;
        float invr = 1.0f / (float)r;
        float liny = (2.0f * sy + 1.0f) * invr - 1.0f;
        float linx = (2.0f * sx + 1.0f) * invr - 1.0f;
        float gy = cy + bh2 * liny;
        float gx = cx + bw2 * linx;
        float iy = ((gy + 1.0f) * (float)HH - 1.0f) * 0.5f;
        float ix = ((gx + 1.0f) * (float)WW - 1.0f) * 0.5f;
        float y0f = floorf(iy), x0f = floorf(ix);
        float wy1 = iy - y0f, wx1 = ix - x0f;
        int y0 = (int)y0f, x0 = (int)x0f;
        int y1i = y0 + 1, x1i = x0 + 1;
        float vx0 = (x0 >= 0 && x0 < WW) ? 1.f : 0.f;
        float vx1 = (x1i >= 0 && x1i < WW) ? 1.f : 0.f;
        float vy0 = (y0 >= 0 && y0 < HH) ? 1.f : 0.f;
        float vy1 = (y1i >= 0 && y1i < HH) ? 1.f : 0.f;
        int x0c = min(max(x0, 0), WW - 1);
        int x1c = min(max(x1i, 0), WW - 1);
        int y0c = min(max(y0, 0), HH - 1);
        int y1c = min(max(y1i, 0), HH - 1);
        s_off[b][0][i] = (y0c * WW + x0c) * 64;
        s_off[b][1][i] = (y0c * WW + x1c) * 64;
        s_off[b][2][i] = (y1c * WW + x0c) * 64;
        s_off[b][3][i] = (y1c * WW + x1c) * 64;
        s_w[b][0][i] = (1.f - wx1) * (1.f - wy1) * vx0 * vy0;
        s_w[b][1][i] = wx1 * (1.f - wy1) * vx1 * vy0;
        s_w[b][2][i] = (1.f - wx1) * wy1 * vx0 * vy1;
        s_w[b][3][i] = wx1 * wy1 * vx1 * vy1;
    }
    __syncthreads();

    int corner = tid >> 4, chunk = tid & 15;
    const int*   off = s_off[b][corner];
    const float* wts = s_w[b][corner];
    float4 a0 = make_float4(0.f, 0.f, 0.f, 0.f);
    float4 a1 = a0, a2 = a0;

#define SAMPLE(ACC, I) { \
        int o = off[I] + chunk * 4; \
        uint2 u = *reinterpret_cast<const uint2*>(&g_fm_h[o]); \
        __half2 h01 = *reinterpret_cast<__half2*>(&u.x); \
        __half2 h23 = *reinterpret_cast<__half2*>(&u.y); \
        float2 f01 = __half22float2(h01); \
        float2 f23 = __half22float2(h23); \
        float w = wts[I]; \
        ACC.x = fmaf(f01.x, w, ACC.x); \
        ACC.y = fmaf(f01.y, w, ACC.y); \
        ACC.z = fmaf(f23.x, w, ACC.z); \
        ACC.w = fmaf(f23.y, w, ACC.w); }

    #pragma unroll 3
    for (int i = 0; i < 9; i++)    SAMPLE(a0, i)
    #pragma unroll 7
    for (int i = 9; i < 58; i++)   SAMPLE(a1, i)
    #pragma unroll 11
    for (int i = 58; i < NSAMP; i++) SAMPLE(a2, i)
#undef SAMPLE

#define RED4(V) { \
        V.x += __shfl_xor_sync(0xffffffffu, V.x, 16); \
        V.y += __shfl_xor_sync(0xffffffffu, V.y, 16); \
        V.z += __shfl_xor_sync(0xffffffffu, V.z, 16); \
        V.w += __shfl_xor_sync(0xffffffffu, V.w, 16); }
    RED4(a0) RED4(a1) RED4(a2)
#undef RED4

    if (tid >= 32 && tid < 48) {
        s_red[b][0][chunk] = a0;
        s_red[b][1][chunk] = a1;
        s_red[b][2][chunk] = a2;
    }
    __syncthreads();
    if (tid < 16) {
        float4 r0 = s_red[b][0][chunk];
        float4 r1 = s_red[b][1][chunk];
        float4 r2 = s_red[b][2][chunk];
        __half2 p0a = __floats2half2_rn((a0.x + r0.x) * (1.f/9.f),  (a0.y + r0.y) * (1.f/9.f));
        __half2 p0b = __floats2half2_rn((a0.z + r0.z) * (1.f/9.f),  (a0.w + r0.w) * (1.f/9.f));
        __half2 p1a = __floats2half2_rn((a1.x + r1.x) * (1.f/49.f), (a1.y + r1.y) * (1.f/49.f));
        __half2 p1b = __floats2half2_rn((a1.z + r1.z) * (1.f/49.f), (a1.w + r1.w) * (1.f/49.f));
        __half2 p2a = __floats2half2_rn((a2.x + r2.x) * (1.f/121.f),(a2.y + r2.y) * (1.f/121.f));
        __half2 p2b = __floats2half2_rn((a2.z + r2.z) * (1.f/121.f),(a2.w + r2.w) * (1.f/121.f));
        uint2 u0 = make_uint2(*(unsigned*)&p0a, *(unsigned*)&p0b);
        uint2 u1 = make_uint2(*(unsigned*)&p1a, *(unsigned*)&p1b);
        uint2 u2 = make_uint2(*(unsigned*)&p2a, *(unsigned*)&p2b);
        *reinterpret_cast<uint2*>(&g_pooled_h[(0 * NBOX + box) * 64 + chunk * 4]) = u0;
        *reinterpret_cast<uint2*>(&g_pooled_h[(1 * NBOX + box) * 64 + chunk * 4]) = u1;
        *reinterpret_cast<uint2*>(&g_pooled_h[(2 * NBOX + box) * 64 + chunk * 4]) = u2;
    }
}

// ---------------------------------------------------------------- shared head (tensor cores): 96 rows/block, grid 128
// smem (bytes): w1h 0..17408, w2h ..35840, Ah ..49664, h1f ..100352, h1h ..126464, c2f ..152576
__global__ void __launch_bounds__(512, 1)
k_head1(const float* __restrict__ w1, const float* __restrict__ b1,
        const float* __restrict__ w2, const float* __restrict__ b2) {
    extern __shared__ char smem[];
    __half* w1h = (__half*)(smem);            // 64 x 136
    __half* w2h = (__half*)(smem + 17408);    // 128 x 72
    __half* Ah  = (__half*)(smem + 35840);    // 96 x 72
    float*  h1f = (float*) (smem + 49664);    // 96 x 132
    __half* h1h = (__half*)(smem + 100352);   // 96 x 136
    float*  c2f = (float*) (smem + 126464);   // 96 x 68

    int t = threadIdx.x;
    int warp = t >> 5;
    int row0 = blockIdx.x * 96;

    for (int i = t; i < 1088; i += 512) ((uint4*)w1h)[i] = ((const uint4*)g_w1h)[i];
    for (int i = t; i < 1152; i += 512) ((uint4*)w2h)[i] = ((const uint4*)g_w2h)[i];
    for (int i = t; i < 96 * 16; i += 512) {
        int r = i >> 4, c4 = i & 15;
        ((uint2*)(Ah + r * 72))[c4] = ((const uint2*)(g_pooled_h + (row0 + r) * 64))[c4];
    }
    __syncthreads();

    // GEMM1: [96x64] @ [64x128] -> h1f. tiles 6x8=48
    for (int tt = warp; tt < 48; tt += 16) {
        int mt = tt >> 3, nt = tt & 7;
        wmma::fragment<wmma::accumulator, 16, 16, 16, float> cf;
        wmma::fill_fragment(cf, 0.f);
        #pragma unroll
        for (int k = 0; k < 4; k++) {
            wmma::fragment<wmma::matrix_a, 16, 16, 16, __half, wmma::row_major> af;
            wmma::fragment<wmma::matrix_b, 16, 16, 16, __half, wmma::row_major> bf;
            wmma::load_matrix_sync(af, Ah + mt * 16 * 72 + k * 16, 72);
            wmma::load_matrix_sync(bf, w1h + k * 16 * 136 + nt * 16, 136);
            wmma::mma_sync(cf, af, bf, cf);
        }
        wmma::store_matrix_sync(h1f + mt * 16 * 132 + nt * 16, cf, 132, wmma::mem_row_major);
    }
    __syncthreads();

    // bias + relu + fp16 convert
    for (int i = t; i < 96 * 128; i += 512) {
        int r = i >> 7, c = i & 127;
        h1h[r * 136 + c] = __float2half_rn(fmaxf(h1f[r * 132 + c] + b1[c], 0.f));
    }
    __syncthreads();

    // GEMM2: [96x128] @ [128x64] -> c2f. tiles 6x4=24
    for (int tt = warp; tt < 24; tt += 16) {
        int mt = tt >> 2, nt = tt & 3;
        wmma::fragment<wmma::accumulator, 16, 16, 16, float> cf;
        wmma::fill_fragment(cf, 0.f);
        #pragma unroll
        for (int k = 0; k < 8; k++) {
            wmma::fragment<wmma::matrix_a, 16, 16, 16, __half, wmma::row_major> af;
            wmma::fragment<wmma::matrix_b, 16, 16, 16, __half, wmma::row_major> bf;
            wmma::load_matrix_sync(af, h1h + mt * 16 * 136 + k * 16, 136);
            wmma::load_matrix_sync(bf, w2h + k * 16 * 72 + nt * 16, 72);
            wmma::mma_sync(cf, af, bf, cf);
        }
        wmma::store_matrix_sync(c2f + mt * 16 * 68 + nt * 16, cf, 68, wmma::mem_row_major);
    }
    __syncthreads();

    // bias + relu + scatter to g_concat (fp16)
    for (int i = t; i < 96 * 64; i += 512) {
        int r = i >> 6, c = i & 63;
        float v = fmaxf(c2f[r * 68 + c] + b2[c], 0.f);
        int gr = row0 + r;
        int s = gr >> 12, bx = gr & 4095;
        g_concat_h[bx * 192 + s * 64 + c] = __float2half_rn(v);
    }

    // block 0 tail: global-mean shared head (fp32, weights from global)
    if (blockIdx.x == 0) {
        __syncthreads();
        float* sred = h1f;
        float* gs   = h1f + 512;
        float* hs   = h1f + 576;
        int c = t & 63, g = t >> 6;
        float v = 0.f;
        for (int bb = g; bb < NTILE; bb += 8) v += g_part[bb * 64 + c];
        sred[t] = v;
        __syncthreads();
        if (t < 64) {
            float s = 0.f;
            #pragma unroll
            for (int q = 0; q < 8; q++) s += sred[t + 64 * q];
            gs[t] = s * (1.0f / (float)NPIX);
        }
        __syncthreads();
        if (t < 128) {
            float a = b1[t];
            #pragma unroll 8
            for (int k = 0; k < 64; k++) a = fmaf(gs[k], w1[k * 128 + t], a);
            hs[t] = fmaxf(a, 0.f);
        }
        __syncthreads();
        if (t < 64) {
            float a = b2[t];
            #pragma unroll 8
            for (int k = 0; k < 128; k++) a = fmaf(hs[k], w2[k * 64 + t], a);
            g_gh_h[t] = __float2half_rn(fmaxf(a, 0.f));
        }
    }
}

// ---------------------------------------------------------------- final fusion (tensor cores): 32 boxes/block, grid 128
// smem: p1h 0..69632, p2h ..88064, xh ..104960, h1f ..121856, h1h ..130560, c2f ..139264
__global__ void __launch_bounds__(512, 1)
k_final(const float* __restrict__ pb1, const float* __restrict__ pb2,
        float* __restrict__ out) {
    extern __shared__ char smem[];
    __half* p1h = (__half*)(smem);            // 256 x 136
    __half* p2h = (__half*)(smem + 69632);    // 128 x 72
    __half* xh  = (__half*)(smem + 88064);    // 32 x 264
    float*  h1f = (float*) (smem + 104960);   // 32 x 132
    __half* h1h = (__half*)(smem + 121856);   // 32 x 136
    float*  c2f = (float*) (smem + 130560);   // 32 x 68

    int t = threadIdx.x;
    int warp = t >> 5;
    int b0 = blockIdx.x * 32;

    for (int i = t; i < 4352; i += 512) ((uint4*)p1h)[i] = ((const uint4*)g_p1h)[i];
    for (int i = t; i < 1152; i += 512) ((uint4*)p2h)[i] = ((const uint4*)g_p2h)[i];
    for (int i = t; i < 32 * 48; i += 512) {
        int r = i / 48, c4 = i - r * 48;
        ((uint2*)(xh + r * 264))[c4] = ((const uint2*)(g_concat_h + (b0 + r) * 192))[c4];
    }
    for (int i = t; i < 32 * 16; i += 512) {
        int r = i >> 4, j = i & 15;
        ((uint2*)(xh + r * 264 + 192))[j] = ((const uint2*)g_gh_h)[j];
    }
    __syncthreads();

    // GEMM3: [32x256] @ [256x128] -> h1f. tiles 2x8=16
    {
        int mt = warp >> 3, nt = warp & 7;
        wmma::fragment<wmma::accumulator, 16, 16, 16, float> cf;
        wmma::fill_fragment(cf, 0.f);
        #pragma unroll
        for (int k = 0; k < 16; k++) {
            wmma::fragment<wmma::matrix_a, 16, 16, 16, __half, wmma::row_major> af;
            wmma::fragment<wmma::matrix_b, 16, 16, 16, __half, wmma::row_major> bf;
            wmma::load_matrix_sync(af, xh + mt * 16 * 264 + k * 16, 264);
            wmma::load_matrix_sync(bf, p1h + k * 16 * 136 + nt * 16, 136);
            wmma::mma_sync(cf, af, bf, cf);
        }
        wmma::store_matrix_sync(h1f + mt * 16 * 132 + nt * 16, cf, 132, wmma::mem_row_major);
    }
    __syncthreads();

    for (int i = t; i < 32 * 128; i += 512) {
        int r = i >> 7, c = i & 127;
        h1h[r * 136 + c] = __float2half_rn(fmaxf(h1f[r * 132 + c] + pb1[c], 0.f));
    }
    __syncthreads();

    // GEMM4: [32x128] @ [128x64] -> c2f. tiles 2x4=8 (warps 0-7)
    if (warp < 8) {
        int mt = warp >> 2, nt = warp & 3;
        wmma::fragment<wmma::accumulator, 16, 16, 16, float> cf;
        wmma::fill_fragment(cf, 0.f);
        #pragma unroll
        for (int k = 0; k < 8; k++) {
            wmma::fragment<wmma::matrix_a, 16, 16, 16, __half, wmma::row_major> af;
            wmma::fragment<wmma::matrix_b, 16, 16, 16, __half, wmma::row_major> bf;
            wmma::load_matrix_sync(af, h1h + mt * 16 * 136 + k * 16, 136);
            wmma::load_matrix_sync(bf, p2h + k * 16 * 72 + nt * 16, 72);
            wmma::mma_sync(cf, af, bf, cf);
        }
        wmma::store_matrix_sync(c2f + mt * 16 * 68 + nt * 16, cf, 68, wmma::mem_row_major);
    }
    __syncthreads();

    for (int i = t; i < 32 * 64; i += 512) {
        int r = i >> 6, c = i & 63;
        out[(b0 + r) * 64 + c] = fmaxf(c2f[r * 68 + c] + pb2[c], 0.f);
    }
}

extern "C" void kernel_launch(void* const* d_in, const int* in_sizes, int n_in,
                              void* d_out, int out_size) {
    const float* fm    = (const float*)d_in[0];
    const float* boxes = (const float*)d_in[1];
    const float* w1    = (const float*)d_in[2];
    const float* b1    = (const float*)d_in[3];
    const float* w2    = (const float*)d_in[4];
    const float* b2    = (const float*)d_in[5];
    const float* p1    = (const float*)d_in[6];
    const float* pb1   = (const float*)d_in[7];
    const float* p2    = (const float*)d_in[8];
    const float* pb2   = (const float*)d_in[9];
    float* out = (float*)d_out;

    const int smem1 = 152576;
    const int smem2 = 139264;
    cudaFuncSetAttribute(k_head1, cudaFuncAttributeMaxDynamicSharedMemorySize, smem1);
    cudaFuncSetAttribute(k_final, cudaFuncAttributeMaxDynamicSharedMemorySize, smem2);

    k_transpose<<<NTILE, dim3(32, 8)>>>(fm);
    k_wconv<<<64, 512>>>(w1, w2, p1, p2);
    k_pool<<<NBOX / 4, 256>>>(boxes);
    k_head1<<<128, 512, smem1>>>(w1, b1, w2, b2);
    k_final<<<128, 512, smem2>>>(pb1, pb2, out);
}